// round 2
// baseline (speedup 1.0000x reference)
#include <cuda_runtime.h>
#include <math.h>

// Problem constants
#define NAK   3
#define NT    300
#define NENT_PER_SCALE (5 * NAK * NT)        // 4500
#define NENT_TOTAL     (3 * NENT_PER_SCALE)  // 13500

#define CELLS0 307200   // 16*3*80*80
#define CELLS1 76800    // 16*3*40*40
#define CELLS2 19200    // 16*3*20*20
#define CELLS_TOTAL (CELLS0 + CELLS1 + CELLS2) // 403200

#define NCELL_BLOCKS (CELLS_TOTAL / 256)     // 1575 (exact)
#define NENT_BLOCKS  ((NENT_TOTAL + 7) / 8)  // 1688 (8 warps/block)

// Scratch: zero at module load; every launch restores zeros before it finishes
// (kernel B resets accumulators/counter, and atomicExch restores g_tobj),
// so graph replays are deterministic.
__device__ double g_lbox[3];
__device__ double g_lcls[3];
__device__ double g_lobj[3];   // softplus part of obj BCE
__device__ int    g_nv[3];
__device__ float  g_tobj[CELLS_TOTAL];
__device__ int    g_list[NENT_TOTAL];
__device__ int    g_listcnt;

__device__ __forceinline__ float softplusf(float x) {
    return fmaxf(x, 0.0f) + log1pf(expf(-fabsf(x)));
}
__device__ __forceinline__ float bce_logits(float x, float t) {
    return softplusf(x) - x * t;
}

// ---------------------------------------------------------------------------
// Kernel A: fused (a) softplus sweep over all obj-channel cells,
//           (b) entry processing: masks, CIoU, cls BCE, tobj scatter-max.
// The two jobs are independent (softplus term doesn't read tobj).
// ---------------------------------------------------------------------------
__global__ void k_main(const float* __restrict__ p0,
                       const float* __restrict__ p1,
                       const float* __restrict__ p2,
                       const float* __restrict__ tg,
                       const float* __restrict__ anchors) {
    if (blockIdx.x < NCELL_BLOCKS) {
        // ---- cell job: sum softplus(obj logit) over all cells ----
        int i = blockIdx.x * 256 + threadIdx.x;   // < CELLS_TOTAL exactly
        int scale, W, base;
        const float* pred;
        if (i < CELLS0)               { scale = 0; W = 80; base = 0;               pred = p0; }
        else if (i < CELLS0 + CELLS1) { scale = 1; W = 40; base = CELLS0;          pred = p1; }
        else                          { scale = 2; W = 20; base = CELLS0 + CELLS1; pred = p2; }
        int idx  = i - base;
        int HW   = W * W;
        int wpos = idx % HW;
        int rest = idx / HW;          // b*3 + a
        int a = rest % 3, b = rest / 3;

        float x = pred[(size_t)(b * 255 + a * 85 + 4) * HW + wpos];
        float val = softplusf(x);

        #pragma unroll
        for (int m = 16; m; m >>= 1) val += __shfl_xor_sync(0xffffffffu, val, m);
        __shared__ float warpsum[8];
        int lane = threadIdx.x & 31, wid = threadIdx.x >> 5;
        if (lane == 0) warpsum[wid] = val;
        __syncthreads();
        if (wid == 0) {
            float s = (lane < 8) ? warpsum[lane] : 0.0f;
            #pragma unroll
            for (int m = 4; m; m >>= 1) s += __shfl_xor_sync(0xffffffffu, s, m);
            if (lane == 0) atomicAdd(&g_lobj[scale], (double)s);
        }
        return;
    }

    // ---- entry job: one warp per (scale, offset, anchor, target) entry ----
    int g    = (blockIdx.x - NCELL_BLOCKS) * 8 + (threadIdx.x >> 5);
    int lane = threadIdx.x & 31;
    if (g >= NENT_TOTAL) return;

    int scale = g / NENT_PER_SCALE;
    int e     = g % NENT_PER_SCALE;
    int o     = e / (NAK * NT);
    int a     = (e % (NAK * NT)) / NT;
    int t     = e % NT;

    int   W = (scale == 0) ? 80 : (scale == 1) ? 40 : 20;
    int   H = W;
    float stride = 640.0f / (float)W;
    const float* pred = (scale == 0) ? p0 : (scale == 1) ? p1 : p2;

    float tbf = tg[t * 6 + 0];
    int   cls = (int)tg[t * 6 + 1];
    float gx  = tg[t * 6 + 2] * (float)W;
    float gy  = tg[t * 6 + 3] * (float)H;
    float gw  = tg[t * 6 + 4] * (float)W;
    float gh  = tg[t * 6 + 5] * (float)H;

    float ax = anchors[(scale * 3 + a) * 2 + 0] / stride;
    float ay = anchors[(scale * 3 + a) * 2 + 1] / stride;

    float rx = gw / ax, ry = gh / ay;
    float rmax = fmaxf(fmaxf(rx, 1.0f / rx), fmaxf(ry, 1.0f / ry));
    bool amask = rmax < 4.0f;

    bool  sel;
    float offx = 0.0f, offy = 0.0f;
    switch (o) {
        case 0: sel = true; break;
        case 1: sel = (fmodf(gx, 1.0f) < 0.5f) && (gx > 1.0f); offx = 1.0f;  break;
        case 2: sel = (fmodf(gy, 1.0f) < 0.5f) && (gy > 1.0f); offy = 1.0f;  break;
        case 3: { float xi = (float)W - gx;
                  sel = (fmodf(xi, 1.0f) < 0.5f) && (xi > 1.0f); offx = -1.0f; } break;
        default:{ float yi = (float)H - gy;
                  sel = (fmodf(yi, 1.0f) < 0.5f) && (yi > 1.0f); offy = -1.0f; } break;
    }
    if (!(sel && amask)) return;   // warp-uniform

    int b    = (int)tbf;
    int gijx = (int)(gx - offx);
    int gijy = (int)(gy - offy);
    int gi = min(max(gijx, 0), W - 1);
    int gj = min(max(gijy, 0), H - 1);

    int HW = H * W;
    const float* base = pred + (size_t)(b * 255 + a * 85) * HW + (size_t)gj * W + gi;

    float csum = 0.0f;
    for (int ch = 5 + lane; ch < 85; ch += 32) {
        float x  = base[(size_t)ch * HW];
        float tt = ((ch - 5) == cls) ? 1.0f : 0.0f;
        csum += bce_logits(x, tt);
    }
    #pragma unroll
    for (int m = 16; m; m >>= 1) csum += __shfl_xor_sync(0xffffffffu, csum, m);

    if (lane == 0) {
        float s0 = base[0];
        float s1 = base[(size_t)1 * HW];
        float s2 = base[(size_t)2 * HW];
        float s3 = base[(size_t)3 * HW];

        float px = 1.0f / (1.0f + expf(-s0));
        float py = 1.0f / (1.0f + expf(-s1));
        float pw = expf(s2) * ax;
        float ph = expf(s3) * ay;
        float tbx = gx - (float)gijx;
        float tby = gy - (float)gijy;

        float b1x1 = px - pw * 0.5f, b1x2 = px + pw * 0.5f;
        float b1y1 = py - ph * 0.5f, b1y2 = py + ph * 0.5f;
        float b2x1 = tbx - gw * 0.5f, b2x2 = tbx + gw * 0.5f;
        float b2y1 = tby - gh * 0.5f, b2y2 = tby + gh * 0.5f;

        float iw = fmaxf(fminf(b1x2, b2x2) - fmaxf(b1x1, b2x1), 0.0f);
        float ih = fmaxf(fminf(b1y2, b2y2) - fmaxf(b1y1, b2y1), 0.0f);
        float inter = iw * ih;
        float w1 = b1x2 - b1x1, h1 = b1y2 - b1y1;
        float w2 = b2x2 - b2x1, h2 = b2y2 - b2y1;
        float uni = w1 * h1 + w2 * h2 - inter + 1e-16f;
        float iou = inter / uni;
        float cw  = fmaxf(b1x2, b2x2) - fminf(b1x1, b2x1);
        float chh = fmaxf(b1y2, b2y2) - fminf(b1y1, b2y1);
        float c2  = cw * cw + chh * chh + 1e-16f;
        float dx  = b2x1 + b2x2 - b1x1 - b1x2;
        float dy  = b2y1 + b2y2 - b1y1 - b1y2;
        float rho2 = (dx * dx + dy * dy) * 0.25f;
        float da = atanf(w2 / h2) - atanf(w1 / h1);
        float v  = (4.0f / (3.14159f * 3.14159f)) * da * da;
        float alpha = v / (v - iou + 1.0f);
        float ciou  = iou - (rho2 / c2 + v * alpha);

        atomicAdd(&g_lbox[scale], (double)(1.0f - ciou));
        atomicAdd(&g_nv[scale], 1);
        atomicAdd(&g_lcls[scale], (double)csum);

        float iou_d = fmaxf(ciou, 0.0f);
        int sbase = (scale == 0) ? 0 : (scale == 1) ? CELLS0 : (CELLS0 + CELLS1);
        int cidx = sbase + ((b * 3 + a) * H + gj) * W + gi;
        atomicMax((int*)&g_tobj[cidx], __float_as_int(iou_d));  // nonneg floats
        int pos = atomicAdd(&g_listcnt, 1);
        g_list[pos] = cidx;
    }
}

// ---------------------------------------------------------------------------
// Kernel B (1 block, 1024 thr): correction term  -x*tobj over touched cells
// (claim each cell once via atomicExch, which also restores tobj to zero),
// then finalize the 4 output scalars and reset all accumulators.
// ---------------------------------------------------------------------------
__global__ void k_final(const float* __restrict__ p0,
                        const float* __restrict__ p1,
                        const float* __restrict__ p2,
                        float* out, int out_size) {
    int tid = threadIdx.x;
    int cnt = g_listcnt;

    double c0 = 0.0, c1 = 0.0, c2s = 0.0;
    for (int e = tid; e < cnt; e += 1024) {
        int i = g_list[e];
        float old = atomicExch(&g_tobj[i], 0.0f);  // claim + reset
        if (old != 0.0f) {
            int scale, W, base;
            const float* pred;
            if (i < CELLS0)               { scale = 0; W = 80; base = 0;               pred = p0; }
            else if (i < CELLS0 + CELLS1) { scale = 1; W = 40; base = CELLS0;          pred = p1; }
            else                          { scale = 2; W = 20; base = CELLS0 + CELLS1; pred = p2; }
            int idx  = i - base;
            int HW   = W * W;
            int wpos = idx % HW;
            int rest = idx / HW;
            int a = rest % 3, b = rest / 3;
            float x = pred[(size_t)(b * 255 + a * 85 + 4) * HW + wpos];
            double term = (double)x * (double)old;
            if (scale == 0) c0 += term; else if (scale == 1) c1 += term; else c2s += term;
        }
    }

    // block-reduce 3 doubles
    #pragma unroll
    for (int m = 16; m; m >>= 1) {
        c0  += __shfl_xor_sync(0xffffffffu, c0,  m);
        c1  += __shfl_xor_sync(0xffffffffu, c1,  m);
        c2s += __shfl_xor_sync(0xffffffffu, c2s, m);
    }
    __shared__ double ws[32][3];
    int lane = tid & 31, wid = tid >> 5;
    if (lane == 0) { ws[wid][0] = c0; ws[wid][1] = c1; ws[wid][2] = c2s; }
    __syncthreads();
    if (tid == 0) {
        double corr[3] = {0.0, 0.0, 0.0};
        for (int w = 0; w < 32; w++) {
            corr[0] += ws[w][0]; corr[1] += ws[w][1]; corr[2] += ws[w][2];
        }
        const double cells[3] = {(double)CELLS0, (double)CELLS1, (double)CELLS2};
        double lbox = 0.0, lobj = 0.0, lcls = 0.0;
        for (int s = 0; s < 3; s++) {
            double nv = (double)g_nv[s];
            lbox += g_lbox[s] / fmax(nv, 1.0);
            lcls += g_lcls[s] / fmax(nv * 80.0, 1.0);
            lobj += (g_lobj[s] - corr[s]) / cells[s];
            // reset for next graph replay
            g_lbox[s] = 0.0; g_lcls[s] = 0.0; g_lobj[s] = 0.0; g_nv[s] = 0;
        }
        g_listcnt = 0;
        lbox *= 0.05;
        lcls *= 0.5;
        double loss = lbox + lobj + lcls;
        out[0] = (float)loss;
        if (out_size >= 4) {
            out[1] = (float)lbox;
            out[2] = (float)lobj;
            out[3] = (float)lcls;
        }
    }
}

extern "C" void kernel_launch(void* const* d_in, const int* in_sizes, int n_in,
                              void* d_out, int out_size) {
    const float* p0      = (const float*)d_in[0];
    const float* p1      = (const float*)d_in[1];
    const float* p2      = (const float*)d_in[2];
    const float* targets = (const float*)d_in[3];
    const float* anchors = (const float*)d_in[4];
    float* out = (float*)d_out;

    k_main<<<NCELL_BLOCKS + NENT_BLOCKS, 256>>>(p0, p1, p2, targets, anchors);
    k_final<<<1, 1024>>>(p0, p1, p2, out, out_size);
}

// round 3
// speedup vs baseline: 1.0531x; 1.0531x over previous
#include <cuda_runtime.h>
#include <math.h>

#define NAK 3
#define NT  300
#define NENT_PER_SCALE 4500            // 5*3*300
#define NENT_TOTAL     13500

#define CELLS0 307200                  // 16*3*80*80
#define CELLS1 76800
#define CELLS2 19200
#define CELLS_TOTAL 403200
#define NVEC (CELLS_TOTAL / 4)         // 100800 float4s
#define NCELL_BLOCKS ((NVEC + 255) / 256)        // 394
#define NENT_BLOCKS  ((NENT_TOTAL + 7) / 8)      // 1688 (8 warps/block)
#define NBLOCKS (NCELL_BLOCKS + NENT_BLOCKS)     // 2082

// Scratch: zero at load; the last block restores all of it to zero each launch,
// so graph replays are deterministic.
__device__ double g_lbox[3];
__device__ double g_lcls[3];
__device__ double g_lobj[3];   // softplus part of obj BCE
__device__ double g_corr[3];   // sum of x * tobj (telescoped deltas)
__device__ int    g_nv[3];
__device__ float  g_tobj[CELLS_TOTAL];
__device__ int    g_list[NENT_TOTAL];
__device__ int    g_listcnt;
__device__ int    g_done;

__device__ __forceinline__ float softplusf(float x) {
    return fmaxf(x, 0.0f) + log1pf(expf(-fabsf(x)));
}

__global__ void __launch_bounds__(256) k_all(
    const float* __restrict__ p0, const float* __restrict__ p1,
    const float* __restrict__ p2, const float* __restrict__ tg,
    const float* __restrict__ anchors, float* out, int out_size)
{
    __shared__ float s_lbox[3], s_lcls[3], s_corr[3];
    __shared__ int   s_nv[3];
    __shared__ float s_warp[8];
    __shared__ int   s_last;
    int tid  = threadIdx.x;
    int lane = tid & 31, wid = tid >> 5;
    if (tid < 3) { s_lbox[tid] = 0.f; s_lcls[tid] = 0.f; s_corr[tid] = 0.f; s_nv[tid] = 0; }
    __syncthreads();

    if (blockIdx.x < NCELL_BLOCKS) {
        // ================= obj softplus sweep (float4, block-uniform scale) ====
        int v = blockIdx.x * 256 + tid;
        int i = v * 4;
        float val = 0.f;
        int scale = 2;                 // inactive tail threads live in scale-2 block
        if (i < CELLS_TOTAL) {
            int W, base; const float* pred;
            if (i < CELLS0)               { scale = 0; W = 80; base = 0;               pred = p0; }
            else if (i < CELLS0 + CELLS1) { scale = 1; W = 40; base = CELLS0;          pred = p1; }
            else                          { scale = 2; W = 20; base = CELLS0 + CELLS1; pred = p2; }
            int idx = i - base, HW = W * W;
            int wpos = idx % HW, rest = idx / HW;   // plane-aligned: HW % 4 == 0
            int a = rest % 3, b = rest / 3;
            float4 x4 = *reinterpret_cast<const float4*>(
                pred + (size_t)(b * 255 + a * 85 + 4) * HW + wpos);
            val = softplusf(x4.x) + softplusf(x4.y) + softplusf(x4.z) + softplusf(x4.w);
        }
        #pragma unroll
        for (int m = 16; m; m >>= 1) val += __shfl_xor_sync(0xffffffffu, val, m);
        if (lane == 0) s_warp[wid] = val;
        __syncthreads();
        if (tid == 0) {
            float s = 0.f;
            #pragma unroll
            for (int w = 0; w < 8; w++) s += s_warp[w];
            atomicAdd(&g_lobj[scale], (double)s);
        }
    } else {
        // ================= entry job: one warp per (scale,offset,anchor,target) =
        int g = (blockIdx.x - NCELL_BLOCKS) * 8 + wid;
        bool active = (g < NENT_TOTAL);
        if (active) {
            int scale = g / NENT_PER_SCALE;
            int e     = g % NENT_PER_SCALE;
            int o     = e / (NAK * NT);
            int a     = (e % (NAK * NT)) / NT;
            int t     = e % NT;

            int   W = (scale == 0) ? 80 : (scale == 1) ? 40 : 20;
            int   H = W;
            float stride = 640.0f / (float)W;
            const float* pred = (scale == 0) ? p0 : (scale == 1) ? p1 : p2;

            float tbf = tg[t * 6 + 0];
            int   cls = (int)tg[t * 6 + 1];
            float gx  = tg[t * 6 + 2] * (float)W;
            float gy  = tg[t * 6 + 3] * (float)H;
            float gw  = tg[t * 6 + 4] * (float)W;
            float gh  = tg[t * 6 + 5] * (float)H;

            float ax = anchors[(scale * 3 + a) * 2 + 0] / stride;
            float ay = anchors[(scale * 3 + a) * 2 + 1] / stride;

            float rx = gw / ax, ry = gh / ay;
            float rmax = fmaxf(fmaxf(rx, 1.0f / rx), fmaxf(ry, 1.0f / ry));
            bool amask = rmax < 4.0f;

            bool  sel;
            float offx = 0.0f, offy = 0.0f;
            switch (o) {
                case 0: sel = true; break;
                case 1: sel = (fmodf(gx, 1.0f) < 0.5f) && (gx > 1.0f); offx = 1.0f;  break;
                case 2: sel = (fmodf(gy, 1.0f) < 0.5f) && (gy > 1.0f); offy = 1.0f;  break;
                case 3: { float xi = (float)W - gx;
                          sel = (fmodf(xi, 1.0f) < 0.5f) && (xi > 1.0f); offx = -1.0f; } break;
                default:{ float yi = (float)H - gy;
                          sel = (fmodf(yi, 1.0f) < 0.5f) && (yi > 1.0f); offy = -1.0f; } break;
            }
            if (sel && amask) {            // warp-uniform
                int b    = (int)tbf;
                int gijx = (int)(gx - offx);
                int gijy = (int)(gy - offy);
                int gi = min(max(gijx, 0), W - 1);
                int gj = min(max(gijy, 0), H - 1);

                int HW = H * W;
                const float* base = pred + (size_t)(b * 255 + a * 85) * HW
                                         + (size_t)gj * W + gi;

                float csum = 0.0f;
                for (int ch = 5 + lane; ch < 85; ch += 32) {
                    float x  = base[(size_t)ch * HW];
                    float tt = ((ch - 5) == cls) ? 1.0f : 0.0f;
                    csum += softplusf(x) - x * tt;
                }
                #pragma unroll
                for (int m = 16; m; m >>= 1) csum += __shfl_xor_sync(0xffffffffu, csum, m);

                if (lane == 0) {
                    float s0 = base[0];
                    float s1 = base[(size_t)1 * HW];
                    float s2 = base[(size_t)2 * HW];
                    float s3 = base[(size_t)3 * HW];
                    float xobj = base[(size_t)4 * HW];

                    float px = 1.0f / (1.0f + expf(-s0));
                    float py = 1.0f / (1.0f + expf(-s1));
                    float pw = expf(s2) * ax;
                    float ph = expf(s3) * ay;
                    float tbx = gx - (float)gijx;
                    float tby = gy - (float)gijy;

                    float b1x1 = px - pw * 0.5f, b1x2 = px + pw * 0.5f;
                    float b1y1 = py - ph * 0.5f, b1y2 = py + ph * 0.5f;
                    float b2x1 = tbx - gw * 0.5f, b2x2 = tbx + gw * 0.5f;
                    float b2y1 = tby - gh * 0.5f, b2y2 = tby + gh * 0.5f;

                    float iw = fmaxf(fminf(b1x2, b2x2) - fmaxf(b1x1, b2x1), 0.0f);
                    float ih = fmaxf(fminf(b1y2, b2y2) - fmaxf(b1y1, b2y1), 0.0f);
                    float inter = iw * ih;
                    float w1 = b1x2 - b1x1, h1 = b1y2 - b1y1;
                    float w2 = b2x2 - b2x1, h2 = b2y2 - b2y1;
                    float uni = w1 * h1 + w2 * h2 - inter + 1e-16f;
                    float iou = inter / uni;
                    float cw  = fmaxf(b1x2, b2x2) - fminf(b1x1, b2x1);
                    float chh = fmaxf(b1y2, b2y2) - fminf(b1y1, b2y1);
                    float c2  = cw * cw + chh * chh + 1e-16f;
                    float dxx = b2x1 + b2x2 - b1x1 - b1x2;
                    float dyy = b2y1 + b2y2 - b1y1 - b1y2;
                    float rho2 = (dxx * dxx + dyy * dyy) * 0.25f;
                    float da = atanf(w2 / h2) - atanf(w1 / h1);
                    float vv = (4.0f / (3.14159f * 3.14159f)) * da * da;
                    float alpha = vv / (vv - iou + 1.0f);
                    float ciou  = iou - (rho2 / c2 + vv * alpha);

                    atomicAdd(&s_lbox[scale], 1.0f - ciou);
                    atomicAdd(&s_lcls[scale], csum);
                    atomicAdd(&s_nv[scale], 1);

                    float iou_d = fmaxf(ciou, 0.0f);
                    int sbase = (scale == 0) ? 0 : (scale == 1) ? CELLS0 : (CELLS0 + CELLS1);
                    int cidx = sbase + ((b * 3 + a) * H + gj) * W + gi;
                    // nonneg floats compare identically as ints; telescoping deltas:
                    int old_i = atomicMax((int*)&g_tobj[cidx], __float_as_int(iou_d));
                    float old_f = __int_as_float(old_i);
                    if (iou_d > old_f)
                        atomicAdd(&s_corr[scale], xobj * (iou_d - old_f));
                    int pos = atomicAdd(&g_listcnt, 1);
                    g_list[pos] = cidx;
                }
            }
        }
        __syncthreads();
        if (tid == 0) {                 // funnel all global flushes through thread 0
            #pragma unroll
            for (int s = 0; s < 3; s++) {
                if (s_nv[s]) {
                    atomicAdd(&g_lbox[s], (double)s_lbox[s]);
                    atomicAdd(&g_lcls[s], (double)s_lcls[s]);
                    atomicAdd(&g_corr[s], (double)s_corr[s]);
                    atomicAdd(&g_nv[s], s_nv[s]);
                }
            }
        }
    }

    // ================= last-block completion =================
    __threadfence();                    // release this thread's global writes
    __syncthreads();
    if (tid == 0) {
        int done = atomicAdd(&g_done, 1);
        s_last = (done == NBLOCKS - 1);
        if (s_last) __threadfence();    // acquire side
    }
    __syncthreads();
    if (s_last) {
        int cnt = g_listcnt;
        for (int e = tid; e < cnt; e += 256) g_tobj[g_list[e]] = 0.0f;  // reset scratch
        if (tid == 0) {
            const double cells[3] = {(double)CELLS0, (double)CELLS1, (double)CELLS2};
            double lbox = 0.0, lobj = 0.0, lcls = 0.0;
            for (int s = 0; s < 3; s++) {
                double nv = (double)g_nv[s];
                lbox += g_lbox[s] / fmax(nv, 1.0);
                lcls += g_lcls[s] / fmax(nv * 80.0, 1.0);
                lobj += (g_lobj[s] - g_corr[s]) / cells[s];
                g_lbox[s] = 0.0; g_lcls[s] = 0.0; g_lobj[s] = 0.0;
                g_corr[s] = 0.0; g_nv[s] = 0;
            }
            g_listcnt = 0;
            g_done = 0;
            lbox *= 0.05;
            lcls *= 0.5;
            double loss = lbox + lobj + lcls;
            out[0] = (float)loss;
            if (out_size >= 4) {
                out[1] = (float)lbox;
                out[2] = (float)lobj;
                out[3] = (float)lcls;
            }
        }
    }
}

extern "C" void kernel_launch(void* const* d_in, const int* in_sizes, int n_in,
                              void* d_out, int out_size) {
    const float* p0      = (const float*)d_in[0];
    const float* p1      = (const float*)d_in[1];
    const float* p2      = (const float*)d_in[2];
    const float* targets = (const float*)d_in[3];
    const float* anchors = (const float*)d_in[4];
    float* out = (float*)d_out;

    k_all<<<NBLOCKS, 256>>>(p0, p1, p2, targets, anchors, out, out_size);
}

// round 4
// speedup vs baseline: 1.1667x; 1.1078x over previous
#include <cuda_runtime.h>
#include <math.h>

#define NAK 3
#define NT  300
#define NENT_PER_SCALE 4500            // 5*3*300
#define NENT_TOTAL     13500

#define CELLS0 307200                  // 16*3*80*80
#define CELLS1 76800
#define CELLS2 19200
#define CELLS_TOTAL 403200
#define NVEC (CELLS_TOTAL / 4)         // 100800 float4s
#define NCELL_BLOCKS ((NVEC + 255) / 256)        // 394
#define NENT_BLOCKS  ((NENT_TOTAL + 7) / 8)      // 1688 (8 warps/block)
#define NBLOCKS (NCELL_BLOCKS + NENT_BLOCKS)     // 2082

// Scratch: zero at load; the last block restores all of it to zero each launch,
// so graph replays are deterministic.
__device__ double g_lbox[3];
__device__ double g_lcls[3];
__device__ double g_lobj[3];   // softplus part of obj BCE
__device__ double g_corr[3];   // sum of x * tobj (telescoped deltas)
__device__ int    g_nv[3];
__device__ float  g_tobj[CELLS_TOTAL];
__device__ int    g_list[NENT_TOTAL];
__device__ int    g_listcnt;
__device__ int    g_done;

// Fast softplus: MUFU-based, ~1e-6 rel err (threshold is 1e-3 on the sum)
__device__ __forceinline__ float softplus_fast(float x) {
    return fmaxf(x, 0.0f) + __logf(1.0f + __expf(-fabsf(x)));
}

__global__ void __launch_bounds__(256) k_all(
    const float* __restrict__ p0, const float* __restrict__ p1,
    const float* __restrict__ p2, const float* __restrict__ tg,
    const float* __restrict__ anchors, float* out, int out_size)
{
    __shared__ float s_lbox[3], s_lcls[3], s_corr[3];
    __shared__ int   s_nv[3];
    __shared__ float s_warp[8];
    __shared__ int   s_last;
    int tid  = threadIdx.x;
    int lane = tid & 31, wid = tid >> 5;
    if (tid < 3) { s_lbox[tid] = 0.f; s_lcls[tid] = 0.f; s_corr[tid] = 0.f; s_nv[tid] = 0; }
    __syncthreads();

    if (blockIdx.x >= NENT_BLOCKS) {
        // ================= obj softplus sweep (float4, block-uniform scale) ====
        int v = (blockIdx.x - NENT_BLOCKS) * 256 + tid;
        int i = v * 4;
        float val = 0.f;
        int scale = 2;                 // inactive tail threads live in scale-2 block
        if (i < CELLS_TOTAL) {
            int W, base; const float* pred;
            if (i < CELLS0)               { scale = 0; W = 80; base = 0;               pred = p0; }
            else if (i < CELLS0 + CELLS1) { scale = 1; W = 40; base = CELLS0;          pred = p1; }
            else                          { scale = 2; W = 20; base = CELLS0 + CELLS1; pred = p2; }
            int idx = i - base, HW = W * W;
            int wpos = idx % HW, rest = idx / HW;   // plane-aligned: HW % 4 == 0
            int a = rest % 3, b = rest / 3;
            float4 x4 = *reinterpret_cast<const float4*>(
                pred + (size_t)(b * 255 + a * 85 + 4) * HW + wpos);
            val = softplus_fast(x4.x) + softplus_fast(x4.y)
                + softplus_fast(x4.z) + softplus_fast(x4.w);
        }
        #pragma unroll
        for (int m = 16; m; m >>= 1) val += __shfl_xor_sync(0xffffffffu, val, m);
        if (lane == 0) s_warp[wid] = val;
        __syncthreads();
        if (tid == 0) {
            float s = 0.f;
            #pragma unroll
            for (int w = 0; w < 8; w++) s += s_warp[w];
            atomicAdd(&g_lobj[scale], (double)s);
        }
    } else {
        // ================= entry job: one warp per (scale,offset,anchor,target) =
        int g = blockIdx.x * 8 + wid;
        if (g < NENT_TOTAL) {
            int scale = g / NENT_PER_SCALE;
            int e     = g % NENT_PER_SCALE;
            int o     = e / (NAK * NT);
            int a     = (e % (NAK * NT)) / NT;
            int t     = e % NT;

            int   W = (scale == 0) ? 80 : (scale == 1) ? 40 : 20;
            int   H = W;
            float stride = 640.0f / (float)W;
            const float* pred = (scale == 0) ? p0 : (scale == 1) ? p1 : p2;

            float tbf = tg[t * 6 + 0];
            int   cls = (int)tg[t * 6 + 1];
            float gx  = tg[t * 6 + 2] * (float)W;
            float gy  = tg[t * 6 + 3] * (float)H;
            float gw  = tg[t * 6 + 4] * (float)W;
            float gh  = tg[t * 6 + 5] * (float)H;

            float ax = anchors[(scale * 3 + a) * 2 + 0] / stride;
            float ay = anchors[(scale * 3 + a) * 2 + 1] / stride;

            float rx = gw / ax, ry = gh / ay;
            float rmax = fmaxf(fmaxf(rx, 1.0f / rx), fmaxf(ry, 1.0f / ry));
            bool amask = rmax < 4.0f;

            bool  sel;
            float offx = 0.0f, offy = 0.0f;
            switch (o) {
                case 0: sel = true; break;
                case 1: sel = (fmodf(gx, 1.0f) < 0.5f) && (gx > 1.0f); offx = 1.0f;  break;
                case 2: sel = (fmodf(gy, 1.0f) < 0.5f) && (gy > 1.0f); offy = 1.0f;  break;
                case 3: { float xi = (float)W - gx;
                          sel = (fmodf(xi, 1.0f) < 0.5f) && (xi > 1.0f); offx = -1.0f; } break;
                default:{ float yi = (float)H - gy;
                          sel = (fmodf(yi, 1.0f) < 0.5f) && (yi > 1.0f); offy = -1.0f; } break;
            }
            if (sel && amask) {            // warp-uniform
                int b    = (int)tbf;
                int gijx = (int)(gx - offx);
                int gijy = (int)(gy - offy);
                int gi = min(max(gijx, 0), W - 1);
                int gj = min(max(gijy, 0), H - 1);

                int HW = H * W;
                const float* base = pred + (size_t)(b * 255 + a * 85) * HW
                                         + (size_t)gj * W + gi;

                float csum = 0.0f;
                for (int ch = 5 + lane; ch < 85; ch += 32) {
                    float x  = base[(size_t)ch * HW];
                    float tt = ((ch - 5) == cls) ? 1.0f : 0.0f;
                    csum += softplus_fast(x) - x * tt;
                }
                #pragma unroll
                for (int m = 16; m; m >>= 1) csum += __shfl_xor_sync(0xffffffffu, csum, m);

                if (lane == 0) {
                    float s0 = base[0];
                    float s1 = base[(size_t)1 * HW];
                    float s2 = base[(size_t)2 * HW];
                    float s3 = base[(size_t)3 * HW];
                    float xobj = base[(size_t)4 * HW];

                    float px = 1.0f / (1.0f + expf(-s0));
                    float py = 1.0f / (1.0f + expf(-s1));
                    float pw = expf(s2) * ax;
                    float ph = expf(s3) * ay;
                    float tbx = gx - (float)gijx;
                    float tby = gy - (float)gijy;

                    float b1x1 = px - pw * 0.5f, b1x2 = px + pw * 0.5f;
                    float b1y1 = py - ph * 0.5f, b1y2 = py + ph * 0.5f;
                    float b2x1 = tbx - gw * 0.5f, b2x2 = tbx + gw * 0.5f;
                    float b2y1 = tby - gh * 0.5f, b2y2 = tby + gh * 0.5f;

                    float iw = fmaxf(fminf(b1x2, b2x2) - fmaxf(b1x1, b2x1), 0.0f);
                    float ih = fmaxf(fminf(b1y2, b2y2) - fmaxf(b1y1, b2y1), 0.0f);
                    float inter = iw * ih;
                    float w1 = b1x2 - b1x1, h1 = b1y2 - b1y1;
                    float w2 = b2x2 - b2x1, h2 = b2y2 - b2y1;
                    float uni = w1 * h1 + w2 * h2 - inter + 1e-16f;
                    float iou = inter / uni;
                    float cw  = fmaxf(b1x2, b2x2) - fminf(b1x1, b2x1);
                    float chh = fmaxf(b1y2, b2y2) - fminf(b1y1, b2y1);
                    float c2  = cw * cw + chh * chh + 1e-16f;
                    float dxx = b2x1 + b2x2 - b1x1 - b1x2;
                    float dyy = b2y1 + b2y2 - b1y1 - b1y2;
                    float rho2 = (dxx * dxx + dyy * dyy) * 0.25f;
                    float da = atanf(w2 / h2) - atanf(w1 / h1);
                    float vv = (4.0f / (3.14159f * 3.14159f)) * da * da;
                    float alpha = vv / (vv - iou + 1.0f);
                    float ciou  = iou - (rho2 / c2 + vv * alpha);

                    atomicAdd(&s_lbox[scale], 1.0f - ciou);
                    atomicAdd(&s_lcls[scale], csum);
                    atomicAdd(&s_nv[scale], 1);

                    float iou_d = fmaxf(ciou, 0.0f);
                    int sbase = (scale == 0) ? 0 : (scale == 1) ? CELLS0 : (CELLS0 + CELLS1);
                    int cidx = sbase + ((b * 3 + a) * H + gj) * W + gi;
                    // nonneg floats compare identically as ints; telescoping deltas:
                    int old_i = atomicMax((int*)&g_tobj[cidx], __float_as_int(iou_d));
                    float old_f = __int_as_float(old_i);
                    if (iou_d > old_f)
                        atomicAdd(&s_corr[scale], xobj * (iou_d - old_f));
                    int pos = atomicAdd(&g_listcnt, 1);
                    g_list[pos] = cidx;
                }
            }
        }
        __syncthreads();
        if (tid == 0) {                 // funnel all global flushes through thread 0
            #pragma unroll
            for (int s = 0; s < 3; s++) {
                if (s_nv[s]) {
                    atomicAdd(&g_lbox[s], (double)s_lbox[s]);
                    atomicAdd(&g_lcls[s], (double)s_lcls[s]);
                    atomicAdd(&g_corr[s], (double)s_corr[s]);
                    atomicAdd(&g_nv[s], s_nv[s]);
                }
            }
        }
    }

    // ================= last-block completion =================
    // All global writes above happen-before tid0 via __syncthreads (CTA scope);
    // tid0's device fence is cumulative over them.
    __syncthreads();
    if (tid == 0) {
        __threadfence();                // release block's writes (cumulative)
        int done = atomicAdd(&g_done, 1);
        s_last = (done == NBLOCKS - 1);
        if (s_last) __threadfence();    // acquire side
    }
    __syncthreads();
    if (s_last) {
        int cnt = g_listcnt;
        for (int e = tid; e < cnt; e += 256) g_tobj[g_list[e]] = 0.0f;  // reset scratch
        if (tid == 0) {
            const double cells[3] = {(double)CELLS0, (double)CELLS1, (double)CELLS2};
            double lbox = 0.0, lobj = 0.0, lcls = 0.0;
            for (int s = 0; s < 3; s++) {
                double nv = (double)g_nv[s];
                lbox += g_lbox[s] / fmax(nv, 1.0);
                lcls += g_lcls[s] / fmax(nv * 80.0, 1.0);
                lobj += (g_lobj[s] - g_corr[s]) / cells[s];
                g_lbox[s] = 0.0; g_lcls[s] = 0.0; g_lobj[s] = 0.0;
                g_corr[s] = 0.0; g_nv[s] = 0;
            }
            g_listcnt = 0;
            g_done = 0;
            lbox *= 0.05;
            lcls *= 0.5;
            double loss = lbox + lobj + lcls;
            out[0] = (float)loss;
            if (out_size >= 4) {
                out[1] = (float)lbox;
                out[2] = (float)lobj;
                out[3] = (float)lcls;
            }
        }
    }
}

extern "C" void kernel_launch(void* const* d_in, const int* in_sizes, int n_in,
                              void* d_out, int out_size) {
    const float* p0      = (const float*)d_in[0];
    const float* p1      = (const float*)d_in[1];
    const float* p2      = (const float*)d_in[2];
    const float* targets = (const float*)d_in[3];
    const float* anchors = (const float*)d_in[4];
    float* out = (float*)d_out;

    k_all<<<NBLOCKS, 256>>>(p0, p1, p2, targets, anchors, out, out_size);
}